// round 16
// baseline (speedup 1.0000x reference)
#include <cuda_runtime.h>
#include <cstdint>

// ---------------- problem constants ----------------
#define B_  8
#define T_  64
#define D_  256
#define H_  1024
#define CPB 8            // CTAs per batch (cluster size)
#define SLICE 128        // H rows per CTA
#define NT  512
#define A2S 272          // A2f row stride (272 % 32banks == 16 -> even/odd disjoint)
#define LR    1e-3f
#define DECAY 0.02f
#define MU    0.9f
#define EPS_  1e-6f

#define CLUSTER_SYNC() do { \
    asm volatile("barrier.cluster.arrive.aligned;" ::: "memory"); \
    asm volatile("barrier.cluster.wait.aligned;"  ::: "memory"); } while (0)

// ---------------- device scratch ----------------
__device__ float g_XN[B_*T_*D_];
__device__ float g_GRAM[B_*T_*T_];
__device__ float g_P1[B_*T_*H_];
// transposed exchange: g_RED1T[b][k][src], rows of 8 floats (32B) -> reduce = 2x LDG.128
__device__ float g_RED1T[B_][324][CPB];

__device__ __forceinline__ uint32_t mapa_rank(uint32_t laddr, int rank)
{
    uint32_t ra;
    asm volatile("mapa.shared::cluster.u32 %0, %1, %2;" : "=r"(ra) : "r"(laddr), "r"(rank));
    return ra;
}
__device__ __forceinline__ void stsc(uint32_t ra, float v)
{
    asm volatile("st.shared::cluster.b32 [%0], %1;" :: "r"(ra), "r"(__float_as_uint(v)) : "memory");
}
__device__ __forceinline__ void mbar_init(uint32_t a, uint32_t cnt)
{
    asm volatile("mbarrier.init.shared.b64 [%0], %1;" :: "r"(a), "r"(cnt) : "memory");
}
__device__ __forceinline__ void mbar_arrive_remote(uint32_t local_addr, int rank)
{
    uint32_t ra = mapa_rank(local_addr, rank);
    asm volatile("mbarrier.arrive.release.cluster.shared::cluster.b64 _, [%0];"
                 :: "r"(ra) : "memory");
}
__device__ __forceinline__ void mbar_wait_cluster(uint32_t a, uint32_t parity)
{
    uint32_t done;
    asm volatile("{\n\t.reg .pred p;\n\t"
        "mbarrier.try_wait.parity.acquire.cluster.shared::cta.b64 p, [%1], %2;\n\t"
        "selp.b32 %0, 1, 0, p;\n\t}"
        : "=r"(done) : "r"(a), "r"(parity) : "memory");
    if (!done) {
        asm volatile("{\n\t.reg .pred P1;\n\t"
            "WAIT_LOOP_%=:\n\t"
            "mbarrier.try_wait.parity.acquire.cluster.shared::cta.b64 P1, [%0], %1, 0x989680;\n\t"
            "@P1 bra.uni WAIT_DONE_%=;\n\t"
            "bra.uni WAIT_LOOP_%=;\n\t"
            "WAIT_DONE_%=:\n\t}"
            :: "r"(a), "r"(parity) : "memory");
    }
}
// packed f32x2 FMA: d += a*b (elementwise on 2 lanes)
__device__ __forceinline__ void ffma2(float2 &d, const float2 a, const float2 b)
{
    unsigned long long *dd = reinterpret_cast<unsigned long long*>(&d);
    asm("fma.rn.f32x2 %0, %1, %2, %0;"
        : "+l"(*dd)
        : "l"(*reinterpret_cast<const unsigned long long*>(&a)),
          "l"(*reinterpret_cast<const unsigned long long*>(&b)));
}

// ---------------- precompute: normalize keys ----------------
__global__ void k_norm(const float* __restrict__ keys)
{
    int bt = blockIdx.x, tid = threadIdx.x;
    float v = keys[bt*D_ + tid];
    float ss = v*v;
    #pragma unroll
    for (int o=16;o;o>>=1) ss += __shfl_xor_sync(~0u, ss, o);
    __shared__ float ws[8];
    __shared__ float s_scale;
    if ((tid&31)==0) ws[tid>>5] = ss;
    __syncthreads();
    if (tid==0) {
        float tot=0.f;
        #pragma unroll
        for (int i=0;i<8;i++) tot += ws[i];
        s_scale = 1.0f / fmaxf(sqrtf(tot), 1e-12f);
    }
    __syncthreads();
    g_XN[bt*D_ + tid] = v * s_scale;
}

// ---------------- precompute: Gram matrix ----------------
__global__ void k_gram()
{
    int bt = blockIdx.x, b = bt / T_, t = bt % T_;
    int tid = threadIdx.x, lane = tid&31, w = tid>>5;
    __shared__ float xt[D_];
    xt[tid] = g_XN[bt*D_ + tid];
    __syncthreads();
    for (int r = w; r < T_; r += 8) {
        const float* xr = &g_XN[(b*T_+r)*D_];
        float acc = 0.f;
        #pragma unroll
        for (int k=lane; k<D_; k+=32) acc += xr[k]*xt[k];
        #pragma unroll
        for (int o=16;o;o>>=1) acc += __shfl_xor_sync(~0u, acc, o);
        if (lane==0) g_GRAM[(b*T_+t)*T_ + r] = acc;
    }
}

// ---------------- precompute: P1 = w1_0 @ xn ----------------
__global__ void k_p1(const float* __restrict__ w1)
{
    int hc = blockIdx.x;   // 32 chunks of 32 H-rows
    int b  = blockIdx.y;
    int tid = threadIdx.x, lane = tid&31, w = tid>>5;
    __shared__ float xns[32][D_];
    for (int half = 0; half < 2; half++) {
        for (int idx = tid; idx < 32*D_; idx += 256) {
            int tt = idx / D_, d = idx % D_;
            xns[tt][d] = g_XN[(b*T_ + half*32 + tt)*D_ + d];
        }
        __syncthreads();
        for (int j = 0; j < 4; j++) {
            int h = hc*32 + w*4 + j;
            float wr[8];
            #pragma unroll
            for (int k=0;k<8;k++) wr[k] = w1[h*D_ + lane + 32*k];
            for (int tt = 0; tt < 32; tt++) {
                float acc = 0.f;
                #pragma unroll
                for (int k=0;k<8;k++) acc += wr[k]*xns[tt][lane + 32*k];
                #pragma unroll
                for (int o=16;o;o>>=1) acc += __shfl_xor_sync(~0u, acc, o);
                if (lane==0) g_P1[(b*T_ + half*32 + tt)*H_ + h] = acc;
            }
        }
        __syncthreads();
    }
}

// ---------------- main kernel ----------------
__global__ __launch_bounds__(NT, 1) __cluster_dims__(CPB, 1, 1)
void k_main(const float* __restrict__ values, const float* __restrict__ w2,
            float* __restrict__ out_preds, float* __restrict__ out_surp)
{
    extern __shared__ float sm[];
    float* B2s  = sm;                        // [64][132] h history
    float* A1f  = B2s  + 64*132;             // [64][132] dh' history
    float* A2f  = A1f  + 64*132;             // [64][A2S] dpred history
    float* fxr  = A2f  + 64*A2S;             // [16][132] backward-dot warp partials
    float* zp   = fxr  + 16*132;             // [512] H combine scratch
    float* h_s  = zp   + 512;                // [128]
    float* gp_s = h_s  + 128;                // [128]
    float* dp_s = gp_s + 128;                // [256]
    float* red_s= dp_s + 256;                // [324]
    float* cf2  = red_s+ 324;                // [64]
    float* cfu  = cf2  + 64;                 // [64]
    float* cf_s = cfu  + 64;                 // [64]
    float* Pc   = cf_s + 64;                 // [64]
    float* Mc   = Pc   + 64;                 // [64]
    float* gr_s = Mc   + 64;                 // [68] next Gram row
    float* rs   = gr_s + 68;                 // [8] hn2 partials (4 used)
    float* rs2  = rs   + 8;                  // [16] dn2 partials (one per warp)
    float* gred2= rs2  + 16;                 // [32] gn2 per (srcCTA, warp) via DSMEM
    float* v_s  = gred2+ 32;                 // [2][256] values double buffer
    float* sc   = v_s  + 512;                // 0=alpha
    unsigned long long* mb = (unsigned long long*)(sc + 8);  // mb[0], mb[1]

    const int tid = threadIdx.x, lane = tid&31, wid = tid>>5;
    const int ti = tid & 15, td = tid >> 4;
    const int b     = blockIdx.x / CPB;
    const int crank = blockIdx.x % CPB;
    const int base  = crank * SLICE;
    const uint32_t mb1a = (uint32_t)__cvta_generic_to_shared(&mb[0]);
    const uint32_t mb2a = (uint32_t)__cvta_generic_to_shared(&mb[1]);

    // ---- register-resident w2 tile, packed along i: w2p[jd][k] = (w[jd][2k], w[jd][2k+1])
    float2 w2p[8][4];
    {
        const float* wbase = w2 + base + ti*8;
        #pragma unroll
        for (int jd=0;jd<8;jd++) {
            const float4* p = (const float4*)(wbase + (td*8+jd)*(size_t)H_);
            float4 x = p[0], y = p[1];
            w2p[jd][0] = make_float2(x.x, x.y);
            w2p[jd][1] = make_float2(x.z, x.w);
            w2p[jd][2] = make_float2(y.x, y.y);
            w2p[jd][3] = make_float2(y.z, y.w);
        }
    }
    if (tid < T_) { Pc[tid] = 0.f; Mc[tid] = 0.f; }
    if (tid==0) {
        sc[0] = 1.0f;
        mbar_init(mb1a, CPB);
        mbar_init(mb2a, CPB);
    }
    __syncthreads();
    CLUSTER_SYNC();          // peers' mbarriers initialized before any remote arrive

    // ---- pre-loop: h_0 = gelu(P1_0); values[0] -> v_s[0] ----
    if (tid < SLICE) {
        float z = g_P1[(b*T_)*H_ + base + tid];
        float ph = 0.5f*(1.0f + erff(z*0.70710678118654752f));
        float h  = z*ph;
        float gp = ph + z*0.39894228040143268f*__expf(-0.5f*z*z);
        h_s[tid] = h; gp_s[tid] = gp; B2s[tid] = h;
        float hh2 = h*h;
        #pragma unroll
        for (int o=16;o;o>>=1) hh2 += __shfl_xor_sync(~0u, hh2, o);
        if (lane==0) rs[wid] = hh2;
    }
    if (tid < D_) v_s[tid] = values[(b*T_)*D_ + tid];
    __syncthreads();

    for (int t = 0; t < T_; t++) {
        const float alpha = sc[0];
        const uint32_t par = (uint32_t)(t & 1);

        // ---- (A) pred partials: packed-f32x2 GEMV -> transposed L2 exchange ----
        {
            const float2* hp = (const float2*)&h_s[ti*8];
            float2 h0 = hp[0], h1 = hp[1], h2 = hp[2], h3 = hp[3];
            float p[8];
            #pragma unroll
            for (int jd=0;jd<8;jd++) {
                float2 a2 = make_float2(0.f, 0.f);
                ffma2(a2, w2p[jd][0], h0);
                ffma2(a2, w2p[jd][1], h1);
                ffma2(a2, w2p[jd][2], h2);
                ffma2(a2, w2p[jd][3], h3);
                p[jd] = a2.x + a2.y;
            }
            #pragma unroll
            for (int jd=0;jd<8;jd++) {
                p[jd] += __shfl_xor_sync(~0u, p[jd], 1);
                p[jd] += __shfl_xor_sync(~0u, p[jd], 2);
                p[jd] += __shfl_xor_sync(~0u, p[jd], 4);
                p[jd] += __shfl_xor_sync(~0u, p[jd], 8);
            }
            if ((lane&15)==0) {
                #pragma unroll
                for (int jd=0;jd<8;jd++)
                    g_RED1T[b][td*8+jd][crank] = p[jd];
            }
        }
        // v_r dots: warp-per-rank, lane-contiguous (conflict-free)
        for (int rr = wid; rr < t; rr += 16) {
            float4 bv = *(const float4*)&B2s[rr*132 + lane*4];
            float4 hv = *(const float4*)&h_s[lane*4];
            float acc = bv.x*hv.x + bv.y*hv.y + bv.z*hv.z + bv.w*hv.w;
            #pragma unroll
            for (int o=16;o;o>>=1) acc += __shfl_xor_sync(~0u, acc, o);
            if (lane==0) g_RED1T[b][256+rr][crank] = acc;
        }
        // hn2 partial
        if (wid==0) {
            float v = (lane<4) ? rs[lane] : 0.f;
            v += __shfl_xor_sync(~0u, v, 1);
            v += __shfl_xor_sync(~0u, v, 2);
            v += __shfl_xor_sync(~0u, v, 4);
            if (lane==0) g_RED1T[b][320][crank] = v;
        }
        __syncthreads();                              // all exchange stores done
        if (wid==0 && lane < CPB) mbar_arrive_remote(mb1a, lane);

        // ---- (B) next-step prefetch (overlaps arrive propagation) ----
        float p1n = 0.f;
        if (t+1 < T_) {
            if (tid <= t+1)  gr_s[tid] = g_GRAM[(b*T_+t+1)*T_ + tid];
            if (tid < SLICE) p1n = g_P1[(b*T_+t+1)*H_ + base + tid];
            if (tid < D_)    v_s[((t+1)&1)*256 + tid] = values[(b*T_+t+1)*D_ + tid];
        }
        mbar_wait_cluster(mb1a, par);

        // ---- (C) reduce partials: 2x LDG.128 per thread ----
        if (tid < 321) {
            const float4* g4 = (const float4*)&g_RED1T[b][tid][0];
            float4 a = g4[0], c = g4[1];
            float s = (a.x+a.y)+(a.z+a.w)+(c.x+c.y)+(c.z+c.w);
            red_s[tid] = s;
            if (tid >= 256 && tid < 320) cf2[tid-256] = Pc[tid-256]*s;
        }
        __syncthreads();

        // ---- (D+pred fused): 2 threads per column, even/odd rank split ----
        {
            int c = tid >> 1, pa = tid & 1;
            float acc = (pa==0) ? alpha * red_s[c] : 0.f;
            for (int r=pa; r<t; r+=2) acc += cf2[r]*A2f[r*A2S + c];
            acc += __shfl_xor_sync(~0u, acc, 1);      // both threads hold full pred
            float dn2p = 0.f;
            if (pa==0) {
                float dp = 2.0f*(acc - v_s[(t&1)*256 + c]);
                dp_s[c] = dp;
                A2f[t*A2S + c] = dp;
                if (crank==0) out_preds[(b*T_+t)*D_ + c] = acc;
                dn2p = dp*dp;
            }
            #pragma unroll
            for (int o=16;o;o>>=1) dn2p += __shfl_xor_sync(~0u, dn2p, o);
            if (lane==0) rs2[wid] = dn2p;
        }
        __syncthreads();

        // ---- (E) u[r] warp-per-rank (conflict-free) + packed backward GEMV ----
        for (int rr = wid; rr < t; rr += 16) {
            const float4* row = (const float4*)(A2f + rr*A2S);
            const float4* dp4 = (const float4*)dp_s;
            float4 a0 = row[lane], a1 = row[32+lane];
            float4 d0 = dp4[lane], d1 = dp4[32+lane];
            float acc = a0.x*d0.x + a0.y*d0.y + a0.z*d0.z + a0.w*d0.w
                      + a1.x*d1.x + a1.y*d1.y + a1.z*d1.z + a1.w*d1.w;
            #pragma unroll
            for (int o=16;o;o>>=1) acc += __shfl_xor_sync(~0u, acc, o);
            if (lane==0) cfu[rr] = Pc[rr]*acc;
        }
        {
            float4 dv0 = *(const float4*)&dp_s[td*8];
            float4 dv1 = *(const float4*)&dp_s[td*8+4];
            float db[8] = {dv0.x,dv0.y,dv0.z,dv0.w,dv1.x,dv1.y,dv1.z,dv1.w};
            float2 fp2[4] = {{0,0},{0,0},{0,0},{0,0}};
            #pragma unroll
            for (int jd=0;jd<8;jd++) {
                float2 dd = make_float2(db[jd], db[jd]);
                ffma2(fp2[0], w2p[jd][0], dd);
                ffma2(fp2[1], w2p[jd][1], dd);
                ffma2(fp2[2], w2p[jd][2], dd);
                ffma2(fp2[3], w2p[jd][3], dd);
            }
            float f[8] = {fp2[0].x, fp2[0].y, fp2[1].x, fp2[1].y,
                          fp2[2].x, fp2[2].y, fp2[3].x, fp2[3].y};
            #pragma unroll
            for (int ji=0;ji<8;ji++) f[ji] += __shfl_xor_sync(~0u, f[ji], 16);
            if (lane < 16) {
                *(float4*)&fxr[wid*132 + ti*8]   = make_float4(f[0],f[1],f[2],f[3]);
                *(float4*)&fxr[wid*132 + ti*8+4] = make_float4(f[4],f[5],f[6],f[7]);
            }
        }
        __syncthreads();

        // ---- (F-combine) 4-way over warp partials + rank loop ----
        {
            int q = tid >> 7, i = tid & 127;
            float s = fxr[(q*4+0)*132+i] + fxr[(q*4+1)*132+i]
                    + fxr[(q*4+2)*132+i] + fxr[(q*4+3)*132+i];
            float acc = alpha * s;
            for (int r=q; r<t; r+=4) acc += cfu[r]*B2s[r*132+i];
            zp[q*128 + i] = acc;
        }
        __syncthreads();

        // ---- (F-final merged with G) ----
        if (tid < SLICE) {
            float dh  = zp[tid] + zp[128+tid] + zp[256+tid] + zp[384+tid];
            float dhp = dh * gp_s[tid];
            A1f[t*132 + tid] = dhp;
            float gn2 = dhp*dhp;
            #pragma unroll
            for (int o=16;o;o>>=1) gn2 += __shfl_xor_sync(~0u, gn2, o);
            if (lane < CPB) {
                uint32_t la = (uint32_t)__cvta_generic_to_shared(&gred2[crank*4 + wid]);
                stsc(mapa_rank(la, lane), gn2);
            }
        } else if (tid >= 128 && tid < 192) {
            int r = tid - 128;
            if (r < t) {
                float m = Mc[r]*MU;
                Mc[r] = m;
                float p = Pc[r]*(1.0f - DECAY) - LR*m;
                Pc[r] = p;
                cf_s[r] = p * gr_s[r];
            }
        } else if (tid == 192) {
            sc[0] = alpha*(1.0f - DECAY);
        }
        __syncthreads();                              // gn2 pushes + recurrences done
        if (wid==0 && lane < CPB) mbar_arrive_remote(mb2a, lane);

        // ---- (H) partial next-z (ranks r<t) overlapped with arrive propagation ----
        {
            int g = tid >> 7, i = tid & 127;
            float z = (g==0) ? (alpha*(1.0f-DECAY))*p1n : 0.f;
            for (int r=g; r<t; r+=4) z += cf_s[r]*A1f[r*132 + i];
            zp[g*128 + i] = z;
        }
        mbar_wait_cluster(mb2a, par);

        // ---- (I) gnorm/clip: every warp reduces redundantly (no broadcast sync) ----
        float cft;
        {
            float a = gred2[lane];                      // 32 (srcCTA, warp) partials
            float c = (lane<16) ? rs2[lane] : 0.f;
            #pragma unroll
            for (int o=16;o;o>>=1) { a += __shfl_xor_sync(~0u, a, o);
                                     c += __shfl_xor_sync(~0u, c, o); }
            float gn = sqrtf(a + c*red_s[320]);         // G[t][t] == 1
            float clip = fminf(1.0f/(gn + EPS_), 1.0f);
            float pt = -LR*clip;
            if (tid==0) {
                Mc[t] = clip; Pc[t] = pt;
                if (crank==0) out_surp[b*T_ + t] = gn;
            }
            cft = (t+1<T_) ? pt*gr_s[t] : 0.f;
        }

        // ---- (K) finish next h: add rank-t term, GELU (no intervening sync) ----
        if (t+1 < T_ && tid < SLICE) {
            float z = zp[tid] + zp[128+tid] + zp[256+tid] + zp[384+tid]
                    + cft*A1f[t*132 + tid];
            float ph = 0.5f*(1.0f + erff(z*0.70710678118654752f));
            float h  = z*ph;
            float gp = ph + z*0.39894228040143268f*__expf(-0.5f*z*z);
            h_s[tid] = h; gp_s[tid] = gp;
            B2s[(t+1)*132 + tid] = h;
            float hh2 = h*h;
            #pragma unroll
            for (int o=16;o;o>>=1) hh2 += __shfl_xor_sync(~0u, hh2, o);
            if (lane==0) rs[wid] = hh2;
        }
        __syncthreads();
    }
}

// ---------------- launch ----------------
extern "C" void kernel_launch(void* const* d_in, const int* in_sizes, int n_in,
                              void* d_out, int out_size)
{
    (void)in_sizes; (void)n_in; (void)out_size;
    const float* keys   = (const float*)d_in[0];
    const float* values = (const float*)d_in[1];
    const float* w1     = (const float*)d_in[2];
    const float* w2     = (const float*)d_in[3];
    float* out       = (float*)d_out;
    float* out_preds = out;                 // [B,T,D]
    float* out_surp  = out + B_*T_*D_;      // [B,T]

    k_norm<<<B_*T_, D_>>>(keys);
    k_gram<<<B_*T_, 256>>>();
    dim3 gp1(H_/32, B_);
    k_p1<<<gp1, 256>>>(w1);

    const size_t f32_cnt =
        (size_t)64*132 + 64*132 + (size_t)64*A2S + 16*132 + 512
        + 128 + 128 + 256 + 324 + 64*5 + 68 + 8 + 16 + 32 + 512 + 8 + 4;
    const size_t smem_bytes = f32_cnt * sizeof(float);
    cudaFuncSetAttribute(k_main, cudaFuncAttributeMaxDynamicSharedMemorySize,
                         (int)smem_bytes);
    k_main<<<B_*CPB, NT, smem_bytes>>>(values, w2, out_preds, out_surp);
}

// round 17
// speedup vs baseline: 1.0491x; 1.0491x over previous
#include <cuda_runtime.h>
#include <cstdint>

// ---------------- problem constants ----------------
#define B_  8
#define T_  64
#define D_  256
#define H_  1024
#define CPB 8            // CTAs per batch (cluster size)
#define SLICE 128        // H rows per CTA
#define NT  512
#define LR    1e-3f
#define DECAY 0.02f
#define MU    0.9f
#define EPS_  1e-6f

#define CLUSTER_SYNC() do { \
    asm volatile("barrier.cluster.arrive.aligned;" ::: "memory"); \
    asm volatile("barrier.cluster.wait.aligned;"  ::: "memory"); } while (0)

// ---------------- device scratch ----------------
__device__ float g_XN[B_*T_*D_];
__device__ float g_GRAM[B_*T_*T_];
__device__ float g_P1[B_*T_*H_];
// transposed exchange: g_RED1T[b][k][src], rows of 8 floats (32B) -> reduce = 2x LDG.128
__device__ float g_RED1T[B_][324][CPB];

__device__ __forceinline__ uint32_t mapa_rank(uint32_t laddr, int rank)
{
    uint32_t ra;
    asm volatile("mapa.shared::cluster.u32 %0, %1, %2;" : "=r"(ra) : "r"(laddr), "r"(rank));
    return ra;
}
__device__ __forceinline__ void stsc(uint32_t ra, float v)
{
    asm volatile("st.shared::cluster.b32 [%0], %1;" :: "r"(ra), "r"(__float_as_uint(v)) : "memory");
}
__device__ __forceinline__ void mbar_init(uint32_t a, uint32_t cnt)
{
    asm volatile("mbarrier.init.shared.b64 [%0], %1;" :: "r"(a), "r"(cnt) : "memory");
}
__device__ __forceinline__ void mbar_arrive_remote(uint32_t local_addr, int rank)
{
    uint32_t ra = mapa_rank(local_addr, rank);
    asm volatile("mbarrier.arrive.release.cluster.shared::cluster.b64 _, [%0];"
                 :: "r"(ra) : "memory");
}
__device__ __forceinline__ void mbar_wait_cluster(uint32_t a, uint32_t parity)
{
    uint32_t done;
    asm volatile("{\n\t.reg .pred p;\n\t"
        "mbarrier.try_wait.parity.acquire.cluster.shared::cta.b64 p, [%1], %2;\n\t"
        "selp.b32 %0, 1, 0, p;\n\t}"
        : "=r"(done) : "r"(a), "r"(parity) : "memory");
    if (!done) {
        asm volatile("{\n\t.reg .pred P1;\n\t"
            "WAIT_LOOP_%=:\n\t"
            "mbarrier.try_wait.parity.acquire.cluster.shared::cta.b64 P1, [%0], %1, 0x989680;\n\t"
            "@P1 bra.uni WAIT_DONE_%=;\n\t"
            "bra.uni WAIT_LOOP_%=;\n\t"
            "WAIT_DONE_%=:\n\t}"
            :: "r"(a), "r"(parity) : "memory");
    }
}

// ---------------- precompute: normalize keys ----------------
__global__ void k_norm(const float* __restrict__ keys)
{
    int bt = blockIdx.x, tid = threadIdx.x;
    float v = keys[bt*D_ + tid];
    float ss = v*v;
    #pragma unroll
    for (int o=16;o;o>>=1) ss += __shfl_xor_sync(~0u, ss, o);
    __shared__ float ws[8];
    __shared__ float s_scale;
    if ((tid&31)==0) ws[tid>>5] = ss;
    __syncthreads();
    if (tid==0) {
        float tot=0.f;
        #pragma unroll
        for (int i=0;i<8;i++) tot += ws[i];
        s_scale = 1.0f / fmaxf(sqrtf(tot), 1e-12f);
    }
    __syncthreads();
    g_XN[bt*D_ + tid] = v * s_scale;
}

// ---------------- precompute: Gram matrix ----------------
__global__ void k_gram()
{
    int bt = blockIdx.x, b = bt / T_, t = bt % T_;
    int tid = threadIdx.x, lane = tid&31, w = tid>>5;
    __shared__ float xt[D_];
    xt[tid] = g_XN[bt*D_ + tid];
    __syncthreads();
    for (int r = w; r < T_; r += 8) {
        const float* xr = &g_XN[(b*T_+r)*D_];
        float acc = 0.f;
        #pragma unroll
        for (int k=lane; k<D_; k+=32) acc += xr[k]*xt[k];
        #pragma unroll
        for (int o=16;o;o>>=1) acc += __shfl_xor_sync(~0u, acc, o);
        if (lane==0) g_GRAM[(b*T_+t)*T_ + r] = acc;
    }
}

// ---------------- precompute: P1 = w1_0 @ xn ----------------
__global__ void k_p1(const float* __restrict__ w1)
{
    int hc = blockIdx.x;   // 32 chunks of 32 H-rows
    int b  = blockIdx.y;
    int tid = threadIdx.x, lane = tid&31, w = tid>>5;
    __shared__ float xns[32][D_];
    for (int half = 0; half < 2; half++) {
        for (int idx = tid; idx < 32*D_; idx += 256) {
            int tt = idx / D_, d = idx % D_;
            xns[tt][d] = g_XN[(b*T_ + half*32 + tt)*D_ + d];
        }
        __syncthreads();
        for (int j = 0; j < 4; j++) {
            int h = hc*32 + w*4 + j;
            float wr[8];
            #pragma unroll
            for (int k=0;k<8;k++) wr[k] = w1[h*D_ + lane + 32*k];
            for (int tt = 0; tt < 32; tt++) {
                float acc = 0.f;
                #pragma unroll
                for (int k=0;k<8;k++) acc += wr[k]*xns[tt][lane + 32*k];
                #pragma unroll
                for (int o=16;o;o>>=1) acc += __shfl_xor_sync(~0u, acc, o);
                if (lane==0) g_P1[(b*T_ + half*32 + tt)*H_ + h] = acc;
            }
        }
        __syncthreads();
    }
}

// ---------------- main kernel ----------------
__global__ __launch_bounds__(NT, 1) __cluster_dims__(CPB, 1, 1)
void k_main(const float* __restrict__ values, const float* __restrict__ w2,
            float* __restrict__ out_preds, float* __restrict__ out_surp)
{
    extern __shared__ float sm[];
    float* B2s  = sm;                        // [64][132] h history
    float* A1f  = B2s  + 64*132;             // [64][132] dh' history
    float* A2f  = A1f  + 64*132;             // [64][264] dpred history
    float* fxr  = A2f  + 64*264;             // [16][132] backward-dot warp partials
    float* zp   = fxr  + 16*132;             // [2048] combine scratch (8 D-groups)
    float* h_s  = zp   + 2048;               // [128]
    float* gp_s = h_s  + 128;                // [128]
    float* dp_s = gp_s + 128;                // [256]
    float* red_s= dp_s + 256;                // [324]
    float* cf2  = red_s+ 324;                // [64]
    float* cfu  = cf2  + 64;                 // [64]
    float* cf_s = cfu  + 64;                 // [64]
    float* Pc   = cf_s + 64;                 // [64]
    float* Mc   = Pc   + 64;                 // [64]
    float* gr_s = Mc   + 64;                 // [68] next Gram row
    float* rs   = gr_s + 68;                 // [8] hn2 partials (4 used)
    float* rs2  = rs   + 8;                  // [8] dn2 partials
    float* gred2= rs2  + 8;                  // [32] gn2 per (srcCTA, warp) via DSMEM
    float* sc   = gred2+ 32;                 // 0=alpha
    unsigned long long* mb = (unsigned long long*)(sc + 8);  // mb[0], mb[1]

    const int tid = threadIdx.x, lane = tid&31, wid = tid>>5;
    const int ti = tid & 15, td = tid >> 4;
    const int b     = blockIdx.x / CPB;
    const int crank = blockIdx.x % CPB;
    const int base  = crank * SLICE;
    const uint32_t mb1a = (uint32_t)__cvta_generic_to_shared(&mb[0]);
    const uint32_t mb2a = (uint32_t)__cvta_generic_to_shared(&mb[1]);

    // ---- register-resident w2 tile ----
    float w2r[8][8];
    {
        const float* wbase = w2 + base + ti*8;
        #pragma unroll
        for (int jd=0;jd<8;jd++) {
            const float4* p = (const float4*)(wbase + (td*8+jd)*(size_t)H_);
            float4 x = p[0], y = p[1];
            w2r[jd][0]=x.x; w2r[jd][1]=x.y; w2r[jd][2]=x.z; w2r[jd][3]=x.w;
            w2r[jd][4]=y.x; w2r[jd][5]=y.y; w2r[jd][6]=y.z; w2r[jd][7]=y.w;
        }
    }
    if (tid < T_) { Pc[tid] = 0.f; Mc[tid] = 0.f; }
    if (tid==0) {
        sc[0] = 1.0f;
        mbar_init(mb1a, CPB);
        mbar_init(mb2a, CPB);
    }
    __syncthreads();
    CLUSTER_SYNC();          // peers' mbarriers initialized before any remote arrive

    // ---- pre-loop: h_0 = gelu(P1_0) ----
    if (tid < SLICE) {
        float z = g_P1[(b*T_)*H_ + base + tid];
        float ph = 0.5f*(1.0f + erff(z*0.70710678118654752f));
        float h  = z*ph;
        float gp = ph + z*0.39894228040143268f*__expf(-0.5f*z*z);
        h_s[tid] = h; gp_s[tid] = gp; B2s[tid] = h;
        float hh2 = h*h;
        #pragma unroll
        for (int o=16;o;o>>=1) hh2 += __shfl_xor_sync(~0u, hh2, o);
        if (lane==0) rs[wid] = hh2;
    }
    float vv  = (tid < D_) ? values[(b*T_)*D_ + tid] : 0.f;
    __syncthreads();

    for (int t = 0; t < T_; t++) {
        const float alpha = sc[0];
        const uint32_t par = (uint32_t)(t & 1);

        // ---- (A) pred partials (register GEMV) -> transposed L2 exchange ----
        {
            float4 hv0 = *(const float4*)&h_s[ti*8];
            float4 hv1 = *(const float4*)&h_s[ti*8+4];
            float hb[8] = {hv0.x,hv0.y,hv0.z,hv0.w,hv1.x,hv1.y,hv1.z,hv1.w};
            float p[8] = {0,0,0,0,0,0,0,0};
            #pragma unroll
            for (int jd=0;jd<8;jd++)
                #pragma unroll
                for (int ii=0;ii<8;ii++) p[jd] += w2r[jd][ii]*hb[ii];
            #pragma unroll
            for (int jd=0;jd<8;jd++) {
                p[jd] += __shfl_xor_sync(~0u, p[jd], 1);
                p[jd] += __shfl_xor_sync(~0u, p[jd], 2);
                p[jd] += __shfl_xor_sync(~0u, p[jd], 4);
                p[jd] += __shfl_xor_sync(~0u, p[jd], 8);
            }
            if ((lane&15)==0) {
                #pragma unroll
                for (int jd=0;jd<8;jd++)
                    g_RED1T[b][td*8+jd][crank] = p[jd];
            }
        }
        // v_r dots: warp-per-rank, lane-contiguous (conflict-free)
        for (int rr = wid; rr < t; rr += 16) {
            float4 bv = *(const float4*)&B2s[rr*132 + lane*4];
            float4 hv = *(const float4*)&h_s[lane*4];
            float acc = bv.x*hv.x + bv.y*hv.y + bv.z*hv.z + bv.w*hv.w;
            #pragma unroll
            for (int o=16;o;o>>=1) acc += __shfl_xor_sync(~0u, acc, o);
            if (lane==0) g_RED1T[b][256+rr][crank] = acc;
        }
        // hn2 partial
        if (wid==0) {
            float v = (lane<4) ? rs[lane] : 0.f;
            v += __shfl_xor_sync(~0u, v, 1);
            v += __shfl_xor_sync(~0u, v, 2);
            v += __shfl_xor_sync(~0u, v, 4);
            if (lane==0) g_RED1T[b][320][crank] = v;
        }
        __syncthreads();                              // all exchange stores done
        if (wid==0 && lane < CPB) mbar_arrive_remote(mb1a, lane);

        // ---- (B) next-step prefetch (overlaps arrive propagation) ----
        float p1n = 0.f, vn = 0.f;
        if (t+1 < T_) {
            if (tid <= t+1)  gr_s[tid] = g_GRAM[(b*T_+t+1)*T_ + tid];
            if (tid < SLICE) p1n = g_P1[(b*T_+t+1)*H_ + base + tid];
            if (tid < D_)    vn  = values[(b*T_+t+1)*D_ + tid];
        }
        mbar_wait_cluster(mb1a, par);

        // ---- (C) reduce partials: 2x LDG.128 per thread ----
        if (tid < 321) {
            const float4* g4 = (const float4*)&g_RED1T[b][tid][0];
            float4 a = g4[0], c = g4[1];
            float s = (a.x+a.y)+(a.z+a.w)+(c.x+c.y)+(c.z+c.w);
            red_s[tid] = s;
            if (tid >= 256 && tid < 320) cf2[tid-256] = Pc[tid-256]*s;
        }
        __syncthreads();

        // ---- (D) pred rank part: 8 rank-groups x 64 float4 columns ----
        {
            int g = tid >> 6, dc = tid & 63;
            float4 a4 = make_float4(0.f,0.f,0.f,0.f);
            if (g==0) {
                float4 rv = *(const float4*)&red_s[4*dc];
                a4.x = alpha*rv.x; a4.y = alpha*rv.y;
                a4.z = alpha*rv.z; a4.w = alpha*rv.w;
            }
            for (int r=g; r<t; r+=8) {
                float c = cf2[r];
                float4 av = *(const float4*)&A2f[r*264 + 4*dc];
                a4.x += c*av.x; a4.y += c*av.y; a4.z += c*av.z; a4.w += c*av.w;
            }
            *(float4*)&zp[g*256 + 4*dc] = a4;
        }
        __syncthreads();
        if (tid < D_) {
            float pr = (zp[tid] + zp[256+tid]) + (zp[512+tid] + zp[768+tid])
                     + (zp[1024+tid] + zp[1280+tid]) + (zp[1536+tid] + zp[1792+tid]);
            float dp = 2.0f*(pr - vv);
            dp_s[tid] = dp;
            A2f[t*264 + tid] = dp;
            if (crank==0) out_preds[(b*T_+t)*D_ + tid] = pr;
            float dn2p = dp*dp;
            #pragma unroll
            for (int o=16;o;o>>=1) dn2p += __shfl_xor_sync(~0u, dn2p, o);
            if (lane==0) rs2[wid] = dn2p;
        }
        __syncthreads();

        // ---- (E) u[r] warp-per-rank (conflict-free) + backward register GEMV ----
        for (int rr = wid; rr < t; rr += 16) {
            const float4* row = (const float4*)(A2f + rr*264);
            const float4* dp4 = (const float4*)dp_s;
            float4 a0 = row[lane], a1 = row[32+lane];
            float4 d0 = dp4[lane], d1 = dp4[32+lane];
            float acc = a0.x*d0.x + a0.y*d0.y + a0.z*d0.z + a0.w*d0.w
                      + a1.x*d1.x + a1.y*d1.y + a1.z*d1.z + a1.w*d1.w;
            #pragma unroll
            for (int o=16;o;o>>=1) acc += __shfl_xor_sync(~0u, acc, o);
            if (lane==0) cfu[rr] = Pc[rr]*acc;
        }
        {
            float4 dv0 = *(const float4*)&dp_s[td*8];
            float4 dv1 = *(const float4*)&dp_s[td*8+4];
            float db[8] = {dv0.x,dv0.y,dv0.z,dv0.w,dv1.x,dv1.y,dv1.z,dv1.w};
            float f[8] = {0,0,0,0,0,0,0,0};
            #pragma unroll
            for (int jd=0;jd<8;jd++)
                #pragma unroll
                for (int ji=0;ji<8;ji++) f[ji] += w2r[jd][ji]*db[jd];
            #pragma unroll
            for (int ji=0;ji<8;ji++) f[ji] += __shfl_xor_sync(~0u, f[ji], 16);
            if (lane < 16) {
                *(float4*)&fxr[wid*132 + ti*8]   = make_float4(f[0],f[1],f[2],f[3]);
                *(float4*)&fxr[wid*132 + ti*8+4] = make_float4(f[4],f[5],f[6],f[7]);
            }
        }
        __syncthreads();

        // ---- (F-combine) 4-way over warp partials + rank loop ----
        // also: dn2 total butterfly hoisted here (overlappable, off the I chain)
        float dn2tot;
        {
            float c = (lane<8) ? rs2[lane] : 0.f;
            #pragma unroll
            for (int o=16;o;o>>=1) c += __shfl_xor_sync(~0u, c, o);
            dn2tot = c;
        }
        {
            int q = tid >> 7, i = tid & 127;
            float s = fxr[(q*4+0)*132+i] + fxr[(q*4+1)*132+i]
                    + fxr[(q*4+2)*132+i] + fxr[(q*4+3)*132+i];
            float acc = alpha * s;
            for (int r=q; r<t; r+=4) acc += cfu[r]*B2s[r*132+i];
            zp[q*128 + i] = acc;
        }
        __syncthreads();

        // ---- (F-final merged with G) ----
        if (tid < SLICE) {
            float dh  = zp[tid] + zp[128+tid] + zp[256+tid] + zp[384+tid];
            float dhp = dh * gp_s[tid];
            A1f[t*132 + tid] = dhp;
            float gn2 = dhp*dhp;
            #pragma unroll
            for (int o=16;o;o>>=1) gn2 += __shfl_xor_sync(~0u, gn2, o);
            if (lane < CPB) {
                uint32_t la = (uint32_t)__cvta_generic_to_shared(&gred2[crank*4 + wid]);
                stsc(mapa_rank(la, lane), gn2);
            }
        } else if (tid >= 128 && tid < 192) {
            int r = tid - 128;
            if (r < t) {
                float m = Mc[r]*MU;
                Mc[r] = m;
                float p = Pc[r]*(1.0f - DECAY) - LR*m;
                Pc[r] = p;
                cf_s[r] = p * gr_s[r];
            }
        } else if (tid == 192) {
            sc[0] = alpha*(1.0f - DECAY);
        }
        __syncthreads();                              // gn2 pushes + recurrences done
        if (wid==0 && lane < CPB) mbar_arrive_remote(mb2a, lane);

        // ---- (H) partial next-z (ranks r<t) overlapped with arrive propagation ----
        {
            int g = tid >> 7, i = tid & 127;
            float z = (g==0) ? (alpha*(1.0f-DECAY))*p1n : 0.f;
            for (int r=g; r<t; r+=4) z += cf_s[r]*A1f[r*132 + i];
            zp[g*128 + i] = z;
        }
        mbar_wait_cluster(mb2a, par);

        // ---- (I) gnorm/clip: gred2 butterfly only (dn2 pre-reduced) ----
        float cft;
        {
            float a = gred2[lane];                      // 32 (srcCTA, warp) partials
            #pragma unroll
            for (int o=16;o;o>>=1) a += __shfl_xor_sync(~0u, a, o);
            float s = a + dn2tot*red_s[320];            // G[t][t] == 1
            float clip = fminf(rsqrtf(s), 1.0f);        // ~= 1/(gn+eps) to ~1e-6 rel
            float pt = -LR*clip;
            if (tid==0) {
                Mc[t] = clip; Pc[t] = pt;
                if (crank==0) out_surp[b*T_ + t] = sqrtf(s);
            }
            cft = (t+1<T_) ? pt*gr_s[t] : 0.f;
        }

        // ---- (K) finish next h: add rank-t term, GELU (no intervening sync) ----
        if (t+1 < T_ && tid < SLICE) {
            float z = zp[tid] + zp[128+tid] + zp[256+tid] + zp[384+tid]
                    + cft*A1f[t*132 + tid];
            float ph = 0.5f*(1.0f + erff(z*0.70710678118654752f));
            float h  = z*ph;
            float gp = ph + z*0.39894228040143268f*__expf(-0.5f*z*z);
            h_s[tid] = h; gp_s[tid] = gp;
            B2s[(t+1)*132 + tid] = h;
            float hh2 = h*h;
            #pragma unroll
            for (int o=16;o;o>>=1) hh2 += __shfl_xor_sync(~0u, hh2, o);
            if (lane==0) rs[wid] = hh2;
        }
        vv = vn;
        __syncthreads();
    }
}

// ---------------- launch ----------------
extern "C" void kernel_launch(void* const* d_in, const int* in_sizes, int n_in,
                              void* d_out, int out_size)
{
    (void)in_sizes; (void)n_in; (void)out_size;
    const float* keys   = (const float*)d_in[0];
    const float* values = (const float*)d_in[1];
    const float* w1     = (const float*)d_in[2];
    const float* w2     = (const float*)d_in[3];
    float* out       = (float*)d_out;
    float* out_preds = out;                 // [B,T,D]
    float* out_surp  = out + B_*T_*D_;      // [B,T]

    k_norm<<<B_*T_, D_>>>(keys);
    k_gram<<<B_*T_, 256>>>();
    dim3 gp1(H_/32, B_);
    k_p1<<<gp1, 256>>>(w1);

    const size_t f32_cnt =
        (size_t)64*132 + 64*132 + 64*264 + 16*132 + 2048
        + 128 + 128 + 256 + 324 + 64*5 + 68 + 8 + 8 + 32 + 8 + 4;
    const size_t smem_bytes = f32_cnt * sizeof(float);
    cudaFuncSetAttribute(k_main, cudaFuncAttributeMaxDynamicSharedMemorySize,
                         (int)smem_bytes);
    k_main<<<B_*CPB, NT, smem_bytes>>>(values, w2, out_preds, out_surp);
}